// round 12
// baseline (speedup 1.0000x reference)
#include <cuda_runtime.h>
#include <math.h>

// ---------------- problem constants ----------------
#define BATCH 64
#define SEQ   512
#define ISZ   1024
#define HSZ   1024
#define MTOT  (BATCH * SEQ)        // 32768 rows of x
#define NCAT  (4 * HSZ)            // 4096 gate columns (i,f,g,o)
#define HSEQ_ELEMS ((size_t)BATCH * SEQ * HSZ)   // 33554432

// ---------------- static device scratch (no allocs allowed) ----------------
__device__ float g_pre[(size_t)MTOT * NCAT];     // 512 MB: input projections + bias
__device__ float g_Wt[4 * HSZ * HSZ];            // 16 MB: W_h transposed to [g][u][k]
__device__ float g_h[2][BATCH * HSZ];            // double-buffered hidden state
__device__ float g_c[BATCH * HSZ];               // cell state

// ============================================================================
// Init: zero h0 and c0
// ============================================================================
__global__ void init_state() {
    int i = blockIdx.x * 256 + threadIdx.x;
    if (i < BATCH * HSZ) {
        g_h[0][i] = 0.0f;
        g_c[i]    = 0.0f;
    }
}

// ============================================================================
// Transpose recurrent weights: g_Wt[g][u][k] = W_h_g[k][u]
// grid (32, 32, 4), block (32, 32)
// ============================================================================
__global__ void transpose_wh(const float* __restrict__ Whi,
                             const float* __restrict__ Whf,
                             const float* __restrict__ Whg,
                             const float* __restrict__ Who) {
    __shared__ float tile[32][33];
    int g = blockIdx.z;
    const float* W = (g == 0) ? Whi : (g == 1) ? Whf : (g == 2) ? Whg : Who;
    int k0 = blockIdx.x * 32;
    int u0 = blockIdx.y * 32;
    int tx = threadIdx.x, ty = threadIdx.y;
    tile[ty][tx] = W[(size_t)(k0 + ty) * HSZ + (u0 + tx)];
    __syncthreads();
    g_Wt[((size_t)g * HSZ + (u0 + ty)) * HSZ + (k0 + tx)] = tile[tx][ty];
}

// ============================================================================
// Phase 1: P[r][g*1024+u] = x[r][:] @ W_x_g[:][u] + bias_g[u]
// r = b*512 + s. Classic 128x128x8 fp32 SGEMM, 256 threads, 8x8 per thread.
// grid (N/128=32, M/128=256)
// ============================================================================
__global__ __launch_bounds__(256) void gemm_x(
    const float* __restrict__ x,
    const float* __restrict__ Wi, const float* __restrict__ Wf,
    const float* __restrict__ Wg, const float* __restrict__ Wo,
    const float* __restrict__ bi, const float* __restrict__ bf,
    const float* __restrict__ bg, const float* __restrict__ bo) {
    __shared__ float As[8][128];
    __shared__ float Bs[8][128];

    const int bx = blockIdx.x;          // N tile (0..31)
    const int by = blockIdx.y;          // M tile (0..255)
    const int t  = threadIdx.x;

    const int gate = (bx * 128) >> 10;          // which gate this N-tile lives in
    const int cb   = (bx * 128) & (HSZ - 1);    // column base within the gate
    const float* W    = (gate == 0) ? Wi : (gate == 1) ? Wf : (gate == 2) ? Wg : Wo;
    const float* bias = (gate == 0) ? bi : (gate == 1) ? bf : (gate == 2) ? bg : bo;

    const int m0 = by * 128;

    const int arow = t >> 1;            // 0..127
    const int aseg = t & 1;             // 0..1 (two float4 per A row of 8)
    const int brow = t >> 5;            // 0..7
    const int bcol = (t & 31) << 2;     // 0..124

    const int ty = t >> 4;              // 0..15 -> 8 output rows each
    const int tx = t & 15;              // 0..15 -> 8 output cols each

    float acc[8][8];
#pragma unroll
    for (int i = 0; i < 8; i++)
#pragma unroll
        for (int j = 0; j < 8; j++) acc[i][j] = 0.0f;

    for (int k0 = 0; k0 < ISZ; k0 += 8) {
        // load A tile (transpose into As[k][m])
        float4 av = *(const float4*)(x + (size_t)(m0 + arow) * ISZ + k0 + aseg * 4);
        As[aseg * 4 + 0][arow] = av.x;
        As[aseg * 4 + 1][arow] = av.y;
        As[aseg * 4 + 2][arow] = av.z;
        As[aseg * 4 + 3][arow] = av.w;
        // load B tile
        *(float4*)(&Bs[brow][bcol]) =
            *(const float4*)(W + (size_t)(k0 + brow) * HSZ + cb + bcol);
        __syncthreads();

#pragma unroll
        for (int kk = 0; kk < 8; kk++) {
            float a[8], b[8];
            *(float4*)(a)     = *(const float4*)(&As[kk][ty * 8]);
            *(float4*)(a + 4) = *(const float4*)(&As[kk][ty * 8 + 4]);
            *(float4*)(b)     = *(const float4*)(&Bs[kk][tx * 8]);
            *(float4*)(b + 4) = *(const float4*)(&Bs[kk][tx * 8 + 4]);
#pragma unroll
            for (int i = 0; i < 8; i++)
#pragma unroll
                for (int j = 0; j < 8; j++)
                    acc[i][j] = fmaf(a[i], b[j], acc[i][j]);
        }
        __syncthreads();
    }

    // epilogue: add bias, store to g_pre
    float bv[8];
#pragma unroll
    for (int j = 0; j < 8; j++) bv[j] = bias[cb + tx * 8 + j];

#pragma unroll
    for (int i = 0; i < 8; i++) {
        size_t ro = (size_t)(m0 + ty * 8 + i) * NCAT + bx * 128 + tx * 8;
        float4 v0, v1;
        v0.x = acc[i][0] + bv[0]; v0.y = acc[i][1] + bv[1];
        v0.z = acc[i][2] + bv[2]; v0.w = acc[i][3] + bv[3];
        v1.x = acc[i][4] + bv[4]; v1.y = acc[i][5] + bv[5];
        v1.z = acc[i][6] + bv[6]; v1.w = acc[i][7] + bv[7];
        *(float4*)(g_pre + ro)     = v0;
        *(float4*)(g_pre + ro + 4) = v1;
    }
}

// ============================================================================
// Phase 2: one timestep.
// 128 blocks x 256 threads. Block bx owns hidden units [bx*8, bx*8+8) for all
// 4 gates and all 64 batches. Streams h (double-buffered) and Wt through smem
// in 32-wide k tiles; 6x LDS.128 per 32 FMA -> FMA-bound.
// Thread t: u = t%8 (local unit), bh = t/8 -> batches bh and bh+32.
// All 4 gates of a (b,u) pair live in one thread -> local pointwise epilogue.
// ============================================================================
__global__ __launch_bounds__(256) void lstm_step(int s, float* __restrict__ hseq) {
    __shared__ float4 hs4[64 * 8];        // [b][kc]  : h tile, 8 KB
    __shared__ float4 ws4[4 * 8 * 8];     // [g][ui][kc] : Wt tile, 4 KB

    const float* __restrict__ hin  = g_h[s & 1];
    float*       __restrict__ hout = g_h[(s + 1) & 1];

    const int t  = threadIdx.x;
    const int u0 = blockIdx.x * 8;
    const int u  = t & 7;
    const int bh = t >> 3;                // 0..31

    float acc0[4] = {0.f, 0.f, 0.f, 0.f};
    float acc1[4] = {0.f, 0.f, 0.f, 0.f};

    for (int k0 = 0; k0 < HSZ; k0 += 32) {
        // load h tile: 512 float4, 2 per thread
        {
            int j = t;
            hs4[j] = *(const float4*)(hin + (j >> 3) * HSZ + k0 + (j & 7) * 4);
            j = t + 256;
            hs4[j] = *(const float4*)(hin + (j >> 3) * HSZ + k0 + (j & 7) * 4);
        }
        // load Wt tile: 256 float4, 1 per thread. layout j = g*64 + ui*8 + kc
        {
            int gg = t >> 6, r = t & 63, ui = r >> 3, kc = r & 7;
            ws4[t] = *(const float4*)(g_Wt + ((size_t)(gg << 10) + (u0 + ui)) * HSZ +
                                      k0 + kc * 4);
        }
        __syncthreads();

#pragma unroll
        for (int kc = 0; kc < 8; kc++) {
            float4 h0 = hs4[bh * 8 + kc];
            float4 h1 = hs4[(bh + 32) * 8 + kc];
#pragma unroll
            for (int gg = 0; gg < 4; gg++) {
                float4 w = ws4[(gg << 6) + (u << 3) + kc];
                acc0[gg] = fmaf(h0.x, w.x, acc0[gg]);
                acc0[gg] = fmaf(h0.y, w.y, acc0[gg]);
                acc0[gg] = fmaf(h0.z, w.z, acc0[gg]);
                acc0[gg] = fmaf(h0.w, w.w, acc0[gg]);
                acc1[gg] = fmaf(h1.x, w.x, acc1[gg]);
                acc1[gg] = fmaf(h1.y, w.y, acc1[gg]);
                acc1[gg] = fmaf(h1.z, w.z, acc1[gg]);
                acc1[gg] = fmaf(h1.w, w.w, acc1[gg]);
            }
        }
        __syncthreads();
    }

    // pointwise epilogue for the 2 (b,u) pairs this thread owns
    const int ug = u0 + u;
#pragma unroll
    for (int p = 0; p < 2; p++) {
        const int b = bh + p * 32;
        const float* a = p ? acc1 : acc0;
        const size_t pb = ((size_t)b * SEQ + s) * NCAT + ug;
        float xi = g_pre[pb]            + a[0];
        float xf = g_pre[pb + HSZ]      + a[1];
        float xg = g_pre[pb + 2 * HSZ]  + a[2];
        float xo = g_pre[pb + 3 * HSZ]  + a[3];
        float ig = 1.0f / (1.0f + expf(-xi));
        float fg = 1.0f / (1.0f + expf(-xf));
        float gv = tanhf(xg);
        float og = 1.0f / (1.0f + expf(-xo));
        const int ci = b * HSZ + ug;
        float cn = fg * g_c[ci] + ig * gv;
        float hn = og * tanhf(cn);
        g_c[ci]  = cn;
        hout[ci] = hn;
        hseq[((size_t)b * SEQ + s) * HSZ + ug] = hn;
    }
}

// ============================================================================
// Final: copy h_T (buffer 0 after step 511) and c_T into d_out tail
// ============================================================================
__global__ void copy_final(float* __restrict__ out) {
    int i = blockIdx.x * 256 + threadIdx.x;
    if (i < BATCH * HSZ) {
        out[HSEQ_ELEMS + i]               = g_h[0][i];   // h_T
        out[HSEQ_ELEMS + BATCH * HSZ + i] = g_c[i];      // c_T
    }
}

// ============================================================================
// launch
// inputs: 0:x 1:W_ii 2:W_hi 3:b_i 4:W_if 5:W_hf 6:b_f 7:W_ig 8:W_hg 9:b_g
//         10:W_io 11:W_ho 12:b_o
// output: hidden_seq (b,s,h) | h_T (b,h) | c_T (b,h), all fp32
// ============================================================================
extern "C" void kernel_launch(void* const* d_in, const int* in_sizes, int n_in,
                              void* d_out, int out_size) {
    const float* x    = (const float*)d_in[0];
    const float* W_ii = (const float*)d_in[1];
    const float* W_hi = (const float*)d_in[2];
    const float* b_i  = (const float*)d_in[3];
    const float* W_if = (const float*)d_in[4];
    const float* W_hf = (const float*)d_in[5];
    const float* b_f  = (const float*)d_in[6];
    const float* W_ig = (const float*)d_in[7];
    const float* W_hg = (const float*)d_in[8];
    const float* b_g  = (const float*)d_in[9];
    const float* W_io = (const float*)d_in[10];
    const float* W_ho = (const float*)d_in[11];
    const float* b_o  = (const float*)d_in[12];
    float* out = (float*)d_out;

    // zero h0, c0
    init_state<<<(BATCH * HSZ + 255) / 256, 256>>>();

    // transpose recurrent weights to [g][u][k]
    transpose_wh<<<dim3(HSZ / 32, HSZ / 32, 4), dim3(32, 32)>>>(W_hi, W_hf, W_hg, W_ho);

    // phase 1: all input projections + bias
    gemm_x<<<dim3(NCAT / 128, MTOT / 128), 256>>>(x, W_ii, W_if, W_ig, W_io,
                                                  b_i, b_f, b_g, b_o);

    // phase 2: sequential recurrence, one launch per timestep
    for (int s = 0; s < SEQ; s++) {
        lstm_step<<<HSZ / 8, 256>>>(s, out);
    }

    // h_T / c_T tail
    copy_final<<<(BATCH * HSZ + 255) / 256, 256>>>(out);
}

// round 13
// speedup vs baseline: 1.0019x; 1.0019x over previous
#include <cuda_runtime.h>
#include <math.h>

// ---------------- problem constants ----------------
#define BATCH 64
#define SEQ   512
#define ISZ   1024
#define HSZ   1024
#define MTOT  (BATCH * SEQ)        // 32768 rows of x
#define NCAT  (4 * HSZ)            // 4096 gate columns (i,f,g,o)
#define HSEQ_ELEMS ((size_t)BATCH * SEQ * HSZ)   // 33554432

// ---------------- static device scratch (no allocs allowed) ----------------
__device__ float g_pre[(size_t)MTOT * NCAT];     // 512 MB: input projections + bias
__device__ float g_Wt[4 * HSZ * HSZ];            // 16 MB: W_h transposed to [g][u][k]
__device__ float g_h[2][BATCH * HSZ];            // double-buffered hidden state
__device__ float g_c[BATCH * HSZ];               // cell state

// ============================================================================
// Init: zero h0 and c0
// ============================================================================
__global__ void init_state() {
    int i = blockIdx.x * 256 + threadIdx.x;
    if (i < BATCH * HSZ) {
        g_h[0][i] = 0.0f;
        g_c[i]    = 0.0f;
    }
}

// ============================================================================
// Transpose recurrent weights: g_Wt[g][u][k] = W_h_g[k][u]
// grid (32, 32, 4), block (32, 32)
// ============================================================================
__global__ void transpose_wh(const float* __restrict__ Whi,
                             const float* __restrict__ Whf,
                             const float* __restrict__ Whg,
                             const float* __restrict__ Who) {
    __shared__ float tile[32][33];
    int g = blockIdx.z;
    const float* W = (g == 0) ? Whi : (g == 1) ? Whf : (g == 2) ? Whg : Who;
    int k0 = blockIdx.x * 32;
    int u0 = blockIdx.y * 32;
    int tx = threadIdx.x, ty = threadIdx.y;
    tile[ty][tx] = W[(size_t)(k0 + ty) * HSZ + (u0 + tx)];
    __syncthreads();
    g_Wt[((size_t)g * HSZ + (u0 + ty)) * HSZ + (k0 + tx)] = tile[tx][ty];
}

// ============================================================================
// Phase 1: P[r][g*1024+u] = x[r][:] @ W_x_g[:][u] + bias_g[u]
// r = b*512 + s. Classic 128x128x8 fp32 SGEMM, 256 threads, 8x8 per thread.
// grid (N/128=32, M/128=256)
// ============================================================================
__global__ __launch_bounds__(256) void gemm_x(
    const float* __restrict__ x,
    const float* __restrict__ Wi, const float* __restrict__ Wf,
    const float* __restrict__ Wg, const float* __restrict__ Wo,
    const float* __restrict__ bi, const float* __restrict__ bf,
    const float* __restrict__ bg, const float* __restrict__ bo) {
    __shared__ float As[8][128];
    __shared__ float Bs[8][128];

    const int bx = blockIdx.x;          // N tile (0..31)
    const int by = blockIdx.y;          // M tile (0..255)
    const int t  = threadIdx.x;

    const int gate = (bx * 128) >> 10;          // which gate this N-tile lives in
    const int cb   = (bx * 128) & (HSZ - 1);    // column base within the gate
    const float* W    = (gate == 0) ? Wi : (gate == 1) ? Wf : (gate == 2) ? Wg : Wo;
    const float* bias = (gate == 0) ? bi : (gate == 1) ? bf : (gate == 2) ? bg : bo;

    const int m0 = by * 128;

    const int arow = t >> 1;            // 0..127
    const int aseg = t & 1;             // 0..1 (two float4 per A row of 8)
    const int brow = t >> 5;            // 0..7
    const int bcol = (t & 31) << 2;     // 0..124

    const int ty = t >> 4;              // 0..15 -> 8 output rows each
    const int tx = t & 15;              // 0..15 -> 8 output cols each

    float acc[8][8];
#pragma unroll
    for (int i = 0; i < 8; i++)
#pragma unroll
        for (int j = 0; j < 8; j++) acc[i][j] = 0.0f;

    for (int k0 = 0; k0 < ISZ; k0 += 8) {
        // load A tile (transpose into As[k][m])
        float4 av = *(const float4*)(x + (size_t)(m0 + arow) * ISZ + k0 + aseg * 4);
        As[aseg * 4 + 0][arow] = av.x;
        As[aseg * 4 + 1][arow] = av.y;
        As[aseg * 4 + 2][arow] = av.z;
        As[aseg * 4 + 3][arow] = av.w;
        // load B tile
        *(float4*)(&Bs[brow][bcol]) =
            *(const float4*)(W + (size_t)(k0 + brow) * HSZ + cb + bcol);
        __syncthreads();

#pragma unroll
        for (int kk = 0; kk < 8; kk++) {
            float a[8], b[8];
            *(float4*)(a)     = *(const float4*)(&As[kk][ty * 8]);
            *(float4*)(a + 4) = *(const float4*)(&As[kk][ty * 8 + 4]);
            *(float4*)(b)     = *(const float4*)(&Bs[kk][tx * 8]);
            *(float4*)(b + 4) = *(const float4*)(&Bs[kk][tx * 8 + 4]);
#pragma unroll
            for (int i = 0; i < 8; i++)
#pragma unroll
                for (int j = 0; j < 8; j++)
                    acc[i][j] = fmaf(a[i], b[j], acc[i][j]);
        }
        __syncthreads();
    }

    // epilogue: add bias, store to g_pre
    float bv[8];
#pragma unroll
    for (int j = 0; j < 8; j++) bv[j] = bias[cb + tx * 8 + j];

#pragma unroll
    for (int i = 0; i < 8; i++) {
        size_t ro = (size_t)(m0 + ty * 8 + i) * NCAT + bx * 128 + tx * 8;
        float4 v0, v1;
        v0.x = acc[i][0] + bv[0]; v0.y = acc[i][1] + bv[1];
        v0.z = acc[i][2] + bv[2]; v0.w = acc[i][3] + bv[3];
        v1.x = acc[i][4] + bv[4]; v1.y = acc[i][5] + bv[5];
        v1.z = acc[i][6] + bv[6]; v1.w = acc[i][7] + bv[7];
        *(float4*)(g_pre + ro)     = v0;
        *(float4*)(g_pre + ro + 4) = v1;
    }
}

// ============================================================================
// Phase 2: one timestep.
// 128 blocks x 256 threads. Block bx owns hidden units [bx*8, bx*8+8) for all
// 4 gates and all 64 batches. Streams h (double-buffered) and Wt through smem
// in 32-wide k tiles; 6x LDS.128 per 32 FMA -> FMA-bound.
// Thread t: u = t%8 (local unit), bh = t/8 -> batches bh and bh+32.
// All 4 gates of a (b,u) pair live in one thread -> local pointwise epilogue.
// ============================================================================
__global__ __launch_bounds__(256) void lstm_step(int s, float* __restrict__ hseq) {
    __shared__ float4 hs4[64 * 8];        // [b][kc]  : h tile, 8 KB
    __shared__ float4 ws4[4 * 8 * 8];     // [g][ui][kc] : Wt tile, 4 KB

    const float* __restrict__ hin  = g_h[s & 1];
    float*       __restrict__ hout = g_h[(s + 1) & 1];

    const int t  = threadIdx.x;
    const int u0 = blockIdx.x * 8;
    const int u  = t & 7;
    const int bh = t >> 3;                // 0..31

    float acc0[4] = {0.f, 0.f, 0.f, 0.f};
    float acc1[4] = {0.f, 0.f, 0.f, 0.f};

    for (int k0 = 0; k0 < HSZ; k0 += 32) {
        // load h tile: 512 float4, 2 per thread
        {
            int j = t;
            hs4[j] = *(const float4*)(hin + (j >> 3) * HSZ + k0 + (j & 7) * 4);
            j = t + 256;
            hs4[j] = *(const float4*)(hin + (j >> 3) * HSZ + k0 + (j & 7) * 4);
        }
        // load Wt tile: 256 float4, 1 per thread. layout j = g*64 + ui*8 + kc
        {
            int gg = t >> 6, r = t & 63, ui = r >> 3, kc = r & 7;
            ws4[t] = *(const float4*)(g_Wt + ((size_t)(gg << 10) + (u0 + ui)) * HSZ +
                                      k0 + kc * 4);
        }
        __syncthreads();

#pragma unroll
        for (int kc = 0; kc < 8; kc++) {
            float4 h0 = hs4[bh * 8 + kc];
            float4 h1 = hs4[(bh + 32) * 8 + kc];
#pragma unroll
            for (int gg = 0; gg < 4; gg++) {
                float4 w = ws4[(gg << 6) + (u << 3) + kc];
                acc0[gg] = fmaf(h0.x, w.x, acc0[gg]);
                acc0[gg] = fmaf(h0.y, w.y, acc0[gg]);
                acc0[gg] = fmaf(h0.z, w.z, acc0[gg]);
                acc0[gg] = fmaf(h0.w, w.w, acc0[gg]);
                acc1[gg] = fmaf(h1.x, w.x, acc1[gg]);
                acc1[gg] = fmaf(h1.y, w.y, acc1[gg]);
                acc1[gg] = fmaf(h1.z, w.z, acc1[gg]);
                acc1[gg] = fmaf(h1.w, w.w, acc1[gg]);
            }
        }
        __syncthreads();
    }

    // pointwise epilogue for the 2 (b,u) pairs this thread owns
    const int ug = u0 + u;
#pragma unroll
    for (int p = 0; p < 2; p++) {
        const int b = bh + p * 32;
        const float* a = p ? acc1 : acc0;
        const size_t pb = ((size_t)b * SEQ + s) * NCAT + ug;
        float xi = g_pre[pb]            + a[0];
        float xf = g_pre[pb + HSZ]      + a[1];
        float xg = g_pre[pb + 2 * HSZ]  + a[2];
        float xo = g_pre[pb + 3 * HSZ]  + a[3];
        float ig = 1.0f / (1.0f + expf(-xi));
        float fg = 1.0f / (1.0f + expf(-xf));
        float gv = tanhf(xg);
        float og = 1.0f / (1.0f + expf(-xo));
        const int ci = b * HSZ + ug;
        float cn = fg * g_c[ci] + ig * gv;
        float hn = og * tanhf(cn);
        g_c[ci]  = cn;
        hout[ci] = hn;
        hseq[((size_t)b * SEQ + s) * HSZ + ug] = hn;
    }
}

// ============================================================================
// Final: copy h_T (buffer 0 after step 511) and c_T into d_out tail
// ============================================================================
__global__ void copy_final(float* __restrict__ out) {
    int i = blockIdx.x * 256 + threadIdx.x;
    if (i < BATCH * HSZ) {
        out[HSEQ_ELEMS + i]               = g_h[0][i];   // h_T
        out[HSEQ_ELEMS + BATCH * HSZ + i] = g_c[i];      // c_T
    }
}

// ============================================================================
// launch
// inputs: 0:x 1:W_ii 2:W_hi 3:b_i 4:W_if 5:W_hf 6:b_f 7:W_ig 8:W_hg 9:b_g
//         10:W_io 11:W_ho 12:b_o
// output: hidden_seq (b,s,h) | h_T (b,h) | c_T (b,h), all fp32
// ============================================================================
extern "C" void kernel_launch(void* const* d_in, const int* in_sizes, int n_in,
                              void* d_out, int out_size) {
    const float* x    = (const float*)d_in[0];
    const float* W_ii = (const float*)d_in[1];
    const float* W_hi = (const float*)d_in[2];
    const float* b_i  = (const float*)d_in[3];
    const float* W_if = (const float*)d_in[4];
    const float* W_hf = (const float*)d_in[5];
    const float* b_f  = (const float*)d_in[6];
    const float* W_ig = (const float*)d_in[7];
    const float* W_hg = (const float*)d_in[8];
    const float* b_g  = (const float*)d_in[9];
    const float* W_io = (const float*)d_in[10];
    const float* W_ho = (const float*)d_in[11];
    const float* b_o  = (const float*)d_in[12];
    float* out = (float*)d_out;

    // zero h0, c0
    init_state<<<(BATCH * HSZ + 255) / 256, 256>>>();

    // transpose recurrent weights to [g][u][k]
    transpose_wh<<<dim3(HSZ / 32, HSZ / 32, 4), dim3(32, 32)>>>(W_hi, W_hf, W_hg, W_ho);

    // phase 1: all input projections + bias
    gemm_x<<<dim3(NCAT / 128, MTOT / 128), 256>>>(x, W_ii, W_if, W_ig, W_io,
                                                  b_i, b_f, b_g, b_o);

    // phase 2: sequential recurrence, one launch per timestep
    for (int s = 0; s < SEQ; s++) {
        lstm_step<<<HSZ / 8, 256>>>(s, out);
    }

    // h_T / c_T tail
    copy_final<<<(BATCH * HSZ + 255) / 256, 256>>>(out);
}